// round 12
// baseline (speedup 1.0000x reference)
#include <cuda_runtime.h>

#define BATCH 256
#define NTOK 256
#define DIMC 256
#define NHEADS 8
#define HD 32
#define NGROUP 64
#define LPOS 961   // (2*16-1)*(2*16-1)
#define TM 32      // mask tile (m-dimension)

typedef unsigned long long u64;

// ---------------- f32x2 packed helpers (Blackwell native dual-fp32) ---------
__device__ __forceinline__ u64 ffma2(u64 a, u64 b, u64 c) {
    u64 d;
    asm("fma.rn.f32x2 %0, %1, %2, %3;" : "=l"(d) : "l"(a), "l"(b), "l"(c));
    return d;
}
__device__ __forceinline__ u64 fmul2(u64 a, u64 b) {
    u64 d;
    asm("mul.rn.f32x2 %0, %1, %2;" : "=l"(d) : "l"(a), "l"(b));
    return d;
}
__device__ __forceinline__ u64 fadd2(u64 a, u64 b) {
    u64 d;
    asm("add.rn.f32x2 %0, %1, %2;" : "=l"(d) : "l"(a), "l"(b));
    return d;
}
__device__ __forceinline__ u64 pack2(float lo, float hi) {
    u64 r;
    asm("mov.b64 %0, {%1,%2};" : "=l"(r) : "f"(lo), "f"(hi));
    return r;
}
__device__ __forceinline__ float2 unpack2(u64 v) {
    float2 f;
    asm("mov.b64 {%0,%1}, %2;" : "=f"(f.x), "=f"(f.y) : "l"(v));
    return f;
}

// ---------------- scratch (static device globals; no runtime allocation) ----
__device__ float g_qh[(size_t)BATCH * NHEADS * NTOK * HD];
__device__ float g_kh[(size_t)BATCH * NHEADS * NTOK * HD];
__device__ float g_vh[(size_t)BATCH * NHEADS * NTOK * HD];
__device__ float g_x [(size_t)BATCH * NTOK * DIMC];
__device__ float g_pos[LPOS * NHEADS];

// ---------------- fast exp: FFMA-only (avoids MUFU bottleneck) --------------
__device__ __forceinline__ float fast_exp(float x) {
    x = fmaxf(x, -80.0f);
    float y = x * 1.4426950408889634f;          // x * log2(e)
    float t = y + 12582912.0f;                  // round-to-nearest via magic
    float n = t - 12582912.0f;
    float f = y - n;                            // f in [-0.5, 0.5]
    int   ni = (int)n;
    float r = 1.3333558146e-3f;                 // 2^f Taylor (exp(f*ln2))
    r = fmaf(r, f, 9.6181291918e-3f);
    r = fmaf(r, f, 5.5504108665e-2f);
    r = fmaf(r, f, 2.4022650696e-1f);
    r = fmaf(r, f, 6.9314718056e-1f);
    r = fmaf(r, f, 1.0f);
    return r * __int_as_float((ni + 127) << 23);
}

// ---------------- DynamicPosBias MLP (961 positions, PD=16, out NH=8) -------
__device__ __forceinline__ void lnorm16(float* x, const float* g, const float* b) {
    float m = 0.f;
    #pragma unroll
    for (int i = 0; i < 16; i++) m += x[i];
    m *= (1.0f / 16.0f);
    float v = 0.f;
    #pragma unroll
    for (int i = 0; i < 16; i++) { float d = x[i] - m; v += d * d; }
    v *= (1.0f / 16.0f);
    float r = rsqrtf(v + 1e-5f);
    #pragma unroll
    for (int i = 0; i < 16; i++) x[i] = (x[i] - m) * r * g[i] + b[i];
}

__global__ void pos_mlp_kernel(
    const float* __restrict__ pp_w, const float* __restrict__ pp_b,
    const float* __restrict__ ln1_g, const float* __restrict__ ln1_b,
    const float* __restrict__ l1_w, const float* __restrict__ l1_b,
    const float* __restrict__ ln2_g, const float* __restrict__ ln2_b,
    const float* __restrict__ l2_w, const float* __restrict__ l2_b,
    const float* __restrict__ ln3_g, const float* __restrict__ ln3_b,
    const float* __restrict__ l3_w, const float* __restrict__ l3_b)
{
    int l = blockIdx.x * blockDim.x + threadIdx.x;
    if (l >= LPOS) return;
    float b0 = (float)(l / 31) - 15.0f;   // bh
    float b1 = (float)(l % 31) - 15.0f;   // bw
    float x[16], y[16];
    #pragma unroll
    for (int p = 0; p < 16; p++)
        x[p] = fmaf(b0, pp_w[p * 2 + 0], fmaf(b1, pp_w[p * 2 + 1], pp_b[p]));
    lnorm16(x, ln1_g, ln1_b);
    #pragma unroll
    for (int p = 0; p < 16; p++) {
        float s = l1_b[p];
        #pragma unroll
        for (int q = 0; q < 16; q++) s = fmaf(fmaxf(x[q], 0.f), l1_w[p * 16 + q], s);
        y[p] = s;
    }
    lnorm16(y, ln2_g, ln2_b);
    #pragma unroll
    for (int p = 0; p < 16; p++) {
        float s = l2_b[p];
        #pragma unroll
        for (int q = 0; q < 16; q++) s = fmaf(fmaxf(y[q], 0.f), l2_w[p * 16 + q], s);
        x[p] = s;
    }
    lnorm16(x, ln3_g, ln3_b);
    #pragma unroll
    for (int h = 0; h < NHEADS; h++) {
        float s = l3_b[h];
        #pragma unroll
        for (int q = 0; q < 16; q++) s = fmaf(fmaxf(x[q], 0.f), l3_w[h * 16 + q], s);
        g_pos[l * NHEADS + h] = s;
    }
}

// ---------------- generic SGEMM (f32x2 inner): C = A @ W^T + bias -----------
// MODE 0: Nout=256, write qh layout (b, h, t, d)
// MODE 1: Nout=512, write kh/vh layouts
// MODE 2: Nout=256, read g_x, write d_out row-major
template<int NOUT, int MODE>
__global__ __launch_bounds__(256)
void gemm_kernel(const float* __restrict__ A_in,
                 const float* __restrict__ Wt,
                 const float* __restrict__ bias,
                 float* __restrict__ Oout)
{
    const int K = 256, BM = 128, BN = 64, BK = 16;
    __shared__ __align__(16) float As[BK][BM];
    __shared__ __align__(16) float Ws[BK][BN];
    const float* A = (MODE == 2) ? g_x : A_in;
    int tid = threadIdx.x;
    int rowBase = blockIdx.x * BM;
    int colBase = blockIdx.y * BN;
    int tx = tid & 15, ty = tid >> 4;

    // acc2[i2][j]: f32x2 holding rows (ty*8+2*i2, ty*8+2*i2+1), col tx*4+j
    u64 acc2[4][4];
    #pragma unroll
    for (int i = 0; i < 4; i++)
        #pragma unroll
        for (int j = 0; j < 4; j++) acc2[i][j] = 0ull;

    for (int k0 = 0; k0 < K; k0 += BK) {
        #pragma unroll
        for (int i = 0; i < 2; i++) {
            int f = tid + i * 256;            // float4 index, 512 total
            int r = f >> 2, kq = (f & 3) * 4;
            float4 v = *(const float4*)&A[(size_t)(rowBase + r) * K + k0 + kq];
            As[kq + 0][r] = v.x; As[kq + 1][r] = v.y;
            As[kq + 2][r] = v.z; As[kq + 3][r] = v.w;
        }
        {
            int c = tid >> 2, kq = (tid & 3) * 4;
            float4 v = *(const float4*)&Wt[(size_t)(colBase + c) * K + k0 + kq];
            Ws[kq + 0][c] = v.x; Ws[kq + 1][c] = v.y;
            Ws[kq + 2][c] = v.z; Ws[kq + 3][c] = v.w;
        }
        __syncthreads();
        #pragma unroll
        for (int k = 0; k < BK; k++) {
            ulonglong2 a01 = *(const ulonglong2*)&As[k][ty * 8];      // row pairs (0,1),(2,3)
            ulonglong2 a23 = *(const ulonglong2*)&As[k][ty * 8 + 4];  // row pairs (4,5),(6,7)
            float4 w4 = *(const float4*)&Ws[k][tx * 4];
            u64 a2[4] = {a01.x, a01.y, a23.x, a23.y};
            u64 wd[4] = {pack2(w4.x, w4.x), pack2(w4.y, w4.y),
                         pack2(w4.z, w4.z), pack2(w4.w, w4.w)};
            #pragma unroll
            for (int i = 0; i < 4; i++)
                #pragma unroll
                for (int j = 0; j < 4; j++)
                    acc2[i][j] = ffma2(a2[i], wd[j], acc2[i][j]);
        }
        __syncthreads();
    }

    #pragma unroll
    for (int j = 0; j < 4; j++) {
        int c = colBase + tx * 4 + j;
        float bv = bias[c];
        #pragma unroll
        for (int i2 = 0; i2 < 4; i2++) {
            float2 pv = unpack2(acc2[i2][j]);
            #pragma unroll
            for (int half2 = 0; half2 < 2; half2++) {
                int r = rowBase + ty * 8 + 2 * i2 + half2;
                float val = (half2 ? pv.y : pv.x) + bv;
                if (MODE == 2) {
                    Oout[(size_t)r * 256 + c] = val;
                } else {
                    int b = r >> 8, t = r & 255;
                    if (MODE == 0) {
                        int h = c / HD, d = c % HD;
                        g_qh[((((size_t)b * NHEADS + h) * NTOK + t) * HD) + d] = val;
                    } else {
                        int half = c >> 8, cc = c & 255;
                        int h = cc / HD, d = cc % HD;
                        size_t off = (((size_t)b * NHEADS + h) * NTOK + t) * HD + d;
                        if (half) g_vh[off] = val; else g_kh[off] = val;
                    }
                }
            }
        }
    }
}

// ---------------- fused attention: per (b,h) CTA, 128 thr, 2 rows/thread ----
// smem: K (8192f) + V (8192f) + pos (961f) + mask tile (256 * 33 f)
#define MT_STRIDE (TM + 1)
#define SMEM_ATTN ((2 * NTOK * HD + LPOS + 3 + NTOK * MT_STRIDE) * sizeof(float))
#define ATHR 128

__global__ __launch_bounds__(ATHR)
void attn_kernel(const float* __restrict__ mask)
{
    extern __shared__ float sm[];
    float* k_s   = sm;                            // 8192
    float* v_s   = sm + NTOK * HD;                // 8192
    float* pos_s = sm + 2 * NTOK * HD;            // 961
    float* mtile = sm + 2 * NTOK * HD + LPOS + 3; // 256*33

    int bh = blockIdx.x;
    int b = bh >> 3, h = bh & 7;
    int tid = threadIdx.x;

    const float4* kb = (const float4*)(g_kh + (size_t)bh * NTOK * HD);
    const float4* vb = (const float4*)(g_vh + (size_t)bh * NTOK * HD);
    #pragma unroll
    for (int i = tid; i < NTOK * HD / 4; i += ATHR) {
        ((float4*)k_s)[i] = kb[i];
        ((float4*)v_s)[i] = vb[i];
    }
    for (int i = tid; i < LPOS; i += ATHR) pos_s[i] = g_pos[i * NHEADS + h];
    __syncthreads();

    // two rows per thread: ta = tid, tb = tid + 128
    int ta = tid, tb = tid + ATHR;
    const float scale = 0.17677669529663687f;   // 1/sqrt(32)
    u64 qa[HD / 2], qb[HD / 2];
    {
        const float4* qra = (const float4*)(g_qh + ((size_t)bh * NTOK + ta) * HD);
        const float4* qrb = (const float4*)(g_qh + ((size_t)bh * NTOK + tb) * HD);
        #pragma unroll
        for (int i = 0; i < HD / 4; i++) {
            float4 va = qra[i], vbq = qrb[i];
            qa[2 * i + 0] = pack2(va.x * scale, va.y * scale);
            qa[2 * i + 1] = pack2(va.z * scale, va.w * scale);
            qb[2 * i + 0] = pack2(vbq.x * scale, vbq.y * scale);
            qb[2 * i + 1] = pack2(vbq.z * scale, vbq.w * scale);
        }
    }
    const float* mbase = mask + (size_t)(b & (NGROUP - 1)) * NTOK * NTOK;
    int th = ta >> 4, tw = ta & 15;   // th_b = th + 8, same tw

    float mxa = -1e30f, suma = 0.f;
    float mxb = -1e30f, sumb = 0.f;
    u64 acca[HD / 2], accb[HD / 2];
    #pragma unroll
    for (int d = 0; d < HD / 2; d++) { acca[d] = 0ull; accb[d] = 0ull; }

    for (int m0 = 0; m0 < NTOK; m0 += TM) {
        // ---- cooperative, coalesced mask tile load: mask[g, 0:256, m0:m0+TM]
        __syncthreads();
        #pragma unroll
        for (int i = 0; i < (NTOK * TM / 4) / ATHR; i++) {
            int f = i * ATHR + tid;           // float4 index
            int r = f >> 3;                   // token row (TM/4 = 8 quads/row)
            int q = f & 7;                    // quad within row
            float4 v4 = *(const float4*)&mbase[(size_t)r * NTOK + m0 + 4 * q];
            float* dst = &mtile[r * MT_STRIDE + 4 * q];
            dst[0] = v4.x; dst[1] = v4.y; dst[2] = v4.z; dst[3] = v4.w;
        }
        __syncthreads();

        const float* mrow_a = &mtile[ta * MT_STRIDE];
        const float* mrow_b = &mtile[tb * MT_STRIDE];

        #pragma unroll 2
        for (int mm = 0; mm < TM; mm++) {
            int m = m0 + mm;
            const ulonglong2* kp = (const ulonglong2*)(k_s + m * HD);
            u64 sa0 = 0ull, sa1 = 0ull, sb0 = 0ull, sb1 = 0ull;
            #pragma unroll
            for (int i = 0; i < 8; i++) {
                ulonglong2 kk = kp[i];          // 4 floats = 2 f32x2 operands
                sa0 = ffma2(qa[2 * i + 0], kk.x, sa0);
                sa1 = ffma2(qa[2 * i + 1], kk.y, sa1);
                sb0 = ffma2(qb[2 * i + 0], kk.x, sb0);
                sb1 = ffma2(qb[2 * i + 1], kk.y, sb1);
            }
            float2 fa = unpack2(fadd2(sa0, sa1));
            float2 fb = unpack2(fadd2(sb0, sb1));
            int mh = m >> 4, mw = m & 15;
            int idx = (th - mh + 15) * 31 + (tw - mw + 15);
            float pos_a = pos_s[idx];
            float pos_b = pos_s[idx + 248];    // th_b = th + 8 -> +8*31
            float s_a = fa.x + fa.y + pos_a + mrow_a[mm];
            float s_b = fb.x + fb.y + pos_b + mrow_b[mm];

            if (s_a > mxa) {                   // rare rescale path
                float corr = fast_exp(mxa - s_a);
                suma *= corr;
                u64 c2 = pack2(corr, corr);
                #pragma unroll
                for (int d = 0; d < HD / 2; d++) acca[d] = fmul2(acca[d], c2);
                mxa = s_a;
            }
            if (s_b > mxb) {
                float corr = fast_exp(mxb - s_b);
                sumb *= corr;
                u64 c2 = pack2(corr, corr);
                #pragma unroll
                for (int d = 0; d < HD / 2; d++) accb[d] = fmul2(accb[d], c2);
                mxb = s_b;
            }
            float p_a = fast_exp(s_a - mxa);
            float p_b = fast_exp(s_b - mxb);
            suma += p_a;
            sumb += p_b;
            u64 pa2 = pack2(p_a, p_a), pb2 = pack2(p_b, p_b);
            const ulonglong2* vp = (const ulonglong2*)(v_s + m * HD);
            #pragma unroll
            for (int i = 0; i < 8; i++) {
                ulonglong2 vv = vp[i];
                acca[2 * i + 0] = ffma2(pa2, vv.x, acca[2 * i + 0]);
                acca[2 * i + 1] = ffma2(pa2, vv.y, acca[2 * i + 1]);
                accb[2 * i + 0] = ffma2(pb2, vv.x, accb[2 * i + 0]);
                accb[2 * i + 1] = ffma2(pb2, vv.y, accb[2 * i + 1]);
            }
        }
    }

    float inva = 1.0f / suma, invb = 1.0f / sumb;
    u64 ia2 = pack2(inva, inva), ib2 = pack2(invb, invb);
    u64* orow_a = (u64*)(g_x + ((size_t)b * NTOK + ta) * DIMC + h * HD);
    u64* orow_b = (u64*)(g_x + ((size_t)b * NTOK + tb) * DIMC + h * HD);
    #pragma unroll
    for (int i = 0; i < HD / 2; i++) {
        orow_a[i] = fmul2(acca[i], ia2);
        orow_b[i] = fmul2(accb[i], ib2);
    }
}

// ---------------- launch ----------------------------------------------------
extern "C" void kernel_launch(void* const* d_in, const int* in_sizes, int n_in,
                              void* d_out, int out_size)
{
    const float* q      = (const float*)d_in[0];
    const float* k      = (const float*)d_in[1];
    const float* mask   = (const float*)d_in[2];
    const float* q_w    = (const float*)d_in[3];
    const float* q_b    = (const float*)d_in[4];
    const float* kv_w   = (const float*)d_in[5];
    const float* kv_b   = (const float*)d_in[6];
    const float* proj_w = (const float*)d_in[7];
    const float* proj_b = (const float*)d_in[8];
    const float* pp_w   = (const float*)d_in[9];
    const float* pp_b   = (const float*)d_in[10];
    const float* ln1_g  = (const float*)d_in[11];
    const float* ln1_b  = (const float*)d_in[12];
    const float* l1_w   = (const float*)d_in[13];
    const float* l1_b   = (const float*)d_in[14];
    const float* ln2_g  = (const float*)d_in[15];
    const float* ln2_b  = (const float*)d_in[16];
    const float* l2_w   = (const float*)d_in[17];
    const float* l2_b   = (const float*)d_in[18];
    const float* ln3_g  = (const float*)d_in[19];
    const float* ln3_b  = (const float*)d_in[20];
    const float* l3_w   = (const float*)d_in[21];
    const float* l3_b   = (const float*)d_in[22];
    float* out = (float*)d_out;

    static int smem_set = 0;
    if (!smem_set) {
        cudaFuncSetAttribute(attn_kernel, cudaFuncAttributeMaxDynamicSharedMemorySize,
                             (int)SMEM_ATTN);
        smem_set = 1;
    }

    pos_mlp_kernel<<<1, 992>>>(pp_w, pp_b, ln1_g, ln1_b, l1_w, l1_b,
                               ln2_g, ln2_b, l2_w, l2_b, ln3_g, ln3_b, l3_w, l3_b);

    // Q projection: (65536,256) x (256,256)^T
    gemm_kernel<256, 0><<<dim3(512, 4), 256>>>(q, q_w, q_b, nullptr);
    // KV projection: (65536,256) x (512,256)^T
    gemm_kernel<512, 1><<<dim3(512, 8), 256>>>(k, kv_w, kv_b, nullptr);
    // fused attention: 2048 CTAs x 128 threads, 2 rows/thread
    attn_kernel<<<BATCH * NHEADS, ATHR, SMEM_ATTN>>>(mask);
    // output projection
    gemm_kernel<256, 2><<<dim3(512, 4), 256>>>(nullptr, proj_w, proj_b, out);
}

// round 14
// speedup vs baseline: 1.6639x; 1.6639x over previous
#include <cuda_runtime.h>
#include <cstdint>

#define BATCH 256
#define NTOK 256
#define DIMC 256
#define NHEADS 8
#define HD 32
#define NGROUP 64
#define LPOS 961   // (2*16-1)*(2*16-1)
#define TM 32      // mask tile (m-dimension)

// ---------------- scratch (static device globals; no runtime allocation) ----
__device__ float g_qh[(size_t)BATCH * NHEADS * NTOK * HD];
__device__ float g_kh[(size_t)BATCH * NHEADS * NTOK * HD];
__device__ float g_vh[(size_t)BATCH * NHEADS * NTOK * HD];
__device__ float g_x [(size_t)BATCH * NTOK * DIMC];
__device__ float g_pos[LPOS * NHEADS];

// ---------------- helpers ----------------------------------------------------
__device__ __forceinline__ uint32_t smem_u32(const void* p) {
    uint32_t a;
    asm("{ .reg .u64 t; cvta.to.shared.u64 t, %1; cvt.u32.u64 %0, t; }"
        : "=r"(a) : "l"(p));
    return a;
}
__device__ __forceinline__ uint32_t f2bf(float f) {   // fp32 -> bf16 bits (RNE)
    uint32_t u = __float_as_uint(f);
    return (u + 0x7fffu + ((u >> 16) & 1u)) >> 16;
}
__device__ __forceinline__ void split2(float a, float b, uint32_t& hi, uint32_t& lo) {
    uint32_t ha = f2bf(a), hb = f2bf(b);
    float ra = a - __uint_as_float(ha << 16);
    float rb = b - __uint_as_float(hb << 16);
    hi = ha | (hb << 16);
    lo = f2bf(ra) | (f2bf(rb) << 16);
}
__device__ __forceinline__ void ldx4(uint32_t* r, uint32_t addr) {
    asm volatile("ldmatrix.sync.aligned.m8n8.x4.shared.b16 {%0,%1,%2,%3}, [%4];"
                 : "=r"(r[0]), "=r"(r[1]), "=r"(r[2]), "=r"(r[3]) : "r"(addr));
}
__device__ __forceinline__ void ldx2(uint32_t& r0, uint32_t& r1, uint32_t addr) {
    asm volatile("ldmatrix.sync.aligned.m8n8.x2.shared.b16 {%0,%1}, [%2];"
                 : "=r"(r0), "=r"(r1) : "r"(addr));
}
__device__ __forceinline__ void mma16816(float* c, const uint32_t* a,
                                         uint32_t b0, uint32_t b1) {
    asm volatile(
        "mma.sync.aligned.m16n8k16.row.col.f32.bf16.bf16.f32 "
        "{%0,%1,%2,%3}, {%4,%5,%6,%7}, {%8,%9}, {%0,%1,%2,%3};"
        : "+f"(c[0]), "+f"(c[1]), "+f"(c[2]), "+f"(c[3])
        : "r"(a[0]), "r"(a[1]), "r"(a[2]), "r"(a[3]), "r"(b0), "r"(b1));
}

// ---------------- fast exp: FFMA-only ---------------------------------------
__device__ __forceinline__ float fast_exp(float x) {
    x = fmaxf(x, -80.0f);
    float y = x * 1.4426950408889634f;
    float t = y + 12582912.0f;
    float n = t - 12582912.0f;
    float f = y - n;
    int   ni = (int)n;
    float r = 1.3333558146e-3f;
    r = fmaf(r, f, 9.6181291918e-3f);
    r = fmaf(r, f, 5.5504108665e-2f);
    r = fmaf(r, f, 2.4022650696e-1f);
    r = fmaf(r, f, 6.9314718056e-1f);
    r = fmaf(r, f, 1.0f);
    return r * __int_as_float((ni + 127) << 23);
}

// ---------------- DynamicPosBias MLP ----------------------------------------
__device__ __forceinline__ void lnorm16(float* x, const float* g, const float* b) {
    float m = 0.f;
    #pragma unroll
    for (int i = 0; i < 16; i++) m += x[i];
    m *= (1.0f / 16.0f);
    float v = 0.f;
    #pragma unroll
    for (int i = 0; i < 16; i++) { float d = x[i] - m; v += d * d; }
    v *= (1.0f / 16.0f);
    float r = rsqrtf(v + 1e-5f);
    #pragma unroll
    for (int i = 0; i < 16; i++) x[i] = (x[i] - m) * r * g[i] + b[i];
}

__global__ void pos_mlp_kernel(
    const float* __restrict__ pp_w, const float* __restrict__ pp_b,
    const float* __restrict__ ln1_g, const float* __restrict__ ln1_b,
    const float* __restrict__ l1_w, const float* __restrict__ l1_b,
    const float* __restrict__ ln2_g, const float* __restrict__ ln2_b,
    const float* __restrict__ l2_w, const float* __restrict__ l2_b,
    const float* __restrict__ ln3_g, const float* __restrict__ ln3_b,
    const float* __restrict__ l3_w, const float* __restrict__ l3_b)
{
    int l = blockIdx.x * blockDim.x + threadIdx.x;
    if (l >= LPOS) return;
    float b0 = (float)(l / 31) - 15.0f;
    float b1 = (float)(l % 31) - 15.0f;
    float x[16], y[16];
    #pragma unroll
    for (int p = 0; p < 16; p++)
        x[p] = fmaf(b0, pp_w[p * 2 + 0], fmaf(b1, pp_w[p * 2 + 1], pp_b[p]));
    lnorm16(x, ln1_g, ln1_b);
    #pragma unroll
    for (int p = 0; p < 16; p++) {
        float s = l1_b[p];
        #pragma unroll
        for (int q = 0; q < 16; q++) s = fmaf(fmaxf(x[q], 0.f), l1_w[p * 16 + q], s);
        y[p] = s;
    }
    lnorm16(y, ln2_g, ln2_b);
    #pragma unroll
    for (int p = 0; p < 16; p++) {
        float s = l2_b[p];
        #pragma unroll
        for (int q = 0; q < 16; q++) s = fmaf(fmaxf(y[q], 0.f), l2_w[p * 16 + q], s);
        x[p] = s;
    }
    lnorm16(x, ln3_g, ln3_b);
    #pragma unroll
    for (int h = 0; h < NHEADS; h++) {
        float s = l3_b[h];
        #pragma unroll
        for (int q = 0; q < 16; q++) s = fmaf(fmaxf(x[q], 0.f), l3_w[h * 16 + q], s);
        g_pos[l * NHEADS + h] = s;
    }
}

// ---------------- HMMA GEMM: C[65536, Nout] = A @ W^T + bias ----------------
// bf16 3-term split via mma.sync m16n8k16 (baseline PTX, works on sm_103).
// Tile: 128x128, K chunks of 64. 8 warps as 2(M) x 4(N); warp tile 64x32.
// smem rows padded to 72 halves (144B) -> conflict-free ldmatrix.
#define KSB 144                       // bytes per smem row (72 halves)
#define AH_OFF 1024
#define AL_OFF (AH_OFF + 128 * KSB)   // 19456
#define WH_OFF (AL_OFF + 128 * KSB)   // 37888
#define WL_OFF (WH_OFF + 128 * KSB)   // 56320
#define GEMM_SMEM (WL_OFF + 128 * KSB)  // 74752

template<int MODE>
__global__ __launch_bounds__(256)
void gemm_mma(const float* __restrict__ A_in,
              const float* __restrict__ Wt,
              const float* __restrict__ bias,
              float* __restrict__ Oout)
{
    extern __shared__ __align__(16) char smem[];
    const float* A = (MODE == 2) ? g_x : A_in;
    int tid = threadIdx.x;
    int rowBase = blockIdx.x * 128;
    int colBase = blockIdx.y * 128;
    uint32_t sb = smem_u32(smem);
    float* bias_s = (float*)smem;
    if (tid < 128) bias_s[tid] = bias[colBase + tid];

    int wid = tid >> 5, l = tid & 31;
    int wm = wid >> 2, wn = wid & 3;

    float c[4][4][4];
    #pragma unroll
    for (int i = 0; i < 4; i++)
        #pragma unroll
        for (int j = 0; j < 4; j++)
            #pragma unroll
            for (int k = 0; k < 4; k++) c[i][j][k] = 0.f;

    // ldmatrix per-lane base offsets
    int mid = l >> 3;
    uint32_t aOffBase = (uint32_t)((wm * 64 + (mid & 1) * 8 + (l & 7)) * KSB
                                   + (mid >> 1) * 16);
    uint32_t bOffBase = (uint32_t)((wn * 32 + (l & 7)) * KSB + ((l >> 3) & 1) * 16);

    for (int ch = 0; ch < 4; ch++) {
        int k0 = ch * 64;
        __syncthreads();                       // smem reuse guard
        #pragma unroll
        for (int i = 0; i < 8; i++) {          // A: 128 x 64 fp32 -> hi/lo bf16
            int idx = i * 256 + tid, row = idx >> 4, q4 = idx & 15;
            float4 v = *(const float4*)&A[(size_t)(rowBase + row) * 256 + k0 + q4 * 4];
            uint32_t h01, l01, h23, l23;
            split2(v.x, v.y, h01, l01);
            split2(v.z, v.w, h23, l23);
            uint32_t off = (uint32_t)(row * KSB + q4 * 8);
            *(uint2*)(smem + AH_OFF + off) = make_uint2(h01, h23);
            *(uint2*)(smem + AL_OFF + off) = make_uint2(l01, l23);
        }
        #pragma unroll
        for (int i = 0; i < 8; i++) {          // W: 128 x 64 fp32 -> hi/lo bf16
            int idx = i * 256 + tid, row = idx >> 4, q4 = idx & 15;
            float4 v = *(const float4*)&Wt[(size_t)(colBase + row) * 256 + k0 + q4 * 4];
            uint32_t h01, l01, h23, l23;
            split2(v.x, v.y, h01, l01);
            split2(v.z, v.w, h23, l23);
            uint32_t off = (uint32_t)(row * KSB + q4 * 8);
            *(uint2*)(smem + WH_OFF + off) = make_uint2(h01, h23);
            *(uint2*)(smem + WL_OFF + off) = make_uint2(l01, l23);
        }
        __syncthreads();

        #pragma unroll
        for (int ks = 0; ks < 4; ks++) {
            uint32_t ah[4][4], al[4][4];
            #pragma unroll
            for (int mt = 0; mt < 4; mt++) {
                uint32_t ao = aOffBase + (uint32_t)(mt * 16 * KSB + ks * 32);
                ldx4(ah[mt], sb + AH_OFF + ao);
                ldx4(al[mt], sb + AL_OFF + ao);
            }
            #pragma unroll
            for (int nt = 0; nt < 4; nt++) {
                uint32_t bo = bOffBase + (uint32_t)(nt * 8 * KSB + ks * 32);
                uint32_t bh0, bh1, bl0, bl1;
                ldx2(bh0, bh1, sb + WH_OFF + bo);
                ldx2(bl0, bl1, sb + WL_OFF + bo);
                #pragma unroll
                for (int mt = 0; mt < 4; mt++) {
                    mma16816(c[mt][nt], ah[mt], bh0, bh1);   // Ahi * Whi
                    mma16816(c[mt][nt], ah[mt], bl0, bl1);   // Ahi * Wlo
                    mma16816(c[mt][nt], al[mt], bh0, bh1);   // Alo * Whi
                }
            }
        }
    }

    // epilogue: bias + direct stores (float2 per reg pair)
    int gRow = l >> 2, gc2 = (l & 3) * 2;
    #pragma unroll
    for (int mt = 0; mt < 4; mt++) {
        #pragma unroll
        for (int nt = 0; nt < 4; nt++) {
            int lc = wn * 32 + nt * 8 + gc2;
            int cg = colBase + lc;
            float bx = bias_s[lc], by = bias_s[lc + 1];
            #pragma unroll
            for (int half = 0; half < 2; half++) {
                int r = rowBase + wm * 64 + mt * 16 + gRow + half * 8;
                float2 o = make_float2(c[mt][nt][half * 2 + 0] + bx,
                                       c[mt][nt][half * 2 + 1] + by);
                if (MODE == 2) {
                    *(float2*)&Oout[(size_t)r * 256 + cg] = o;
                } else {
                    int b = r >> 8, t = r & 255;
                    if (MODE == 0) {
                        int h = cg >> 5, d = cg & 31;
                        *(float2*)&g_qh[((((size_t)b * NHEADS + h) * NTOK + t) * HD) + d] = o;
                    } else {
                        int hv = cg >> 8, cc = cg & 255;
                        int h = cc >> 5, d = cc & 31;
                        float* dst = hv ? g_vh : g_kh;
                        *(float2*)&dst[((((size_t)b * NHEADS + h) * NTOK + t) * HD) + d] = o;
                    }
                }
            }
        }
    }
}

// ---------------- fused attention (R7 known-good): per (b,h) CTA ------------
#define MT_STRIDE (TM + 1)
#define SMEM_ATTN ((2 * NTOK * HD + LPOS + 3 + NTOK * MT_STRIDE) * sizeof(float))

__global__ __launch_bounds__(256)
void attn_kernel(const float* __restrict__ mask)
{
    extern __shared__ float sm[];
    float* k_s   = sm;
    float* v_s   = sm + NTOK * HD;
    float* pos_s = sm + 2 * NTOK * HD;
    float* mtile = sm + 2 * NTOK * HD + LPOS + 3;

    int bh = blockIdx.x;
    int b = bh >> 3, h = bh & 7;
    int tid = threadIdx.x;

    const float4* kb = (const float4*)(g_kh + (size_t)bh * NTOK * HD);
    const float4* vb = (const float4*)(g_vh + (size_t)bh * NTOK * HD);
    #pragma unroll
    for (int i = tid; i < NTOK * HD / 4; i += 256) {
        ((float4*)k_s)[i] = kb[i];
        ((float4*)v_s)[i] = vb[i];
    }
    for (int i = tid; i < LPOS; i += 256) pos_s[i] = g_pos[i * NHEADS + h];
    __syncthreads();

    int t = tid;
    const float scale = 0.17677669529663687f;
    float qr[HD];
    {
        const float4* qrow = (const float4*)(g_qh + ((size_t)bh * NTOK + t) * HD);
        #pragma unroll
        for (int i = 0; i < HD / 4; i++) {
            float4 v4 = qrow[i];
            qr[4 * i + 0] = v4.x * scale; qr[4 * i + 1] = v4.y * scale;
            qr[4 * i + 2] = v4.z * scale; qr[4 * i + 3] = v4.w * scale;
        }
    }
    const float* mbase = mask + (size_t)(b & (NGROUP - 1)) * NTOK * NTOK;
    int th = t >> 4, tw = t & 15;

    float mx = -1e30f, ssum = 0.f;
    float acc[HD];
    #pragma unroll
    for (int d = 0; d < HD; d++) acc[d] = 0.f;

    for (int m0 = 0; m0 < NTOK; m0 += TM) {
        __syncthreads();
        #pragma unroll
        for (int i = 0; i < (NTOK * TM / 4) / 256; i++) {
            int f = i * 256 + tid;
            int r = f >> 3;
            int q = f & 7;
            float4 v4 = *(const float4*)&mbase[(size_t)r * NTOK + m0 + 4 * q];
            float* dst = &mtile[r * MT_STRIDE + 4 * q];
            dst[0] = v4.x; dst[1] = v4.y; dst[2] = v4.z; dst[3] = v4.w;
        }
        __syncthreads();

        const float* mrow_s = &mtile[t * MT_STRIDE];

        #pragma unroll 2
        for (int mm = 0; mm < TM; mm++) {
            int m = m0 + mm;
            const float4* kv = (const float4*)(k_s + m * HD);
            float s0 = 0.f, s1 = 0.f, s2 = 0.f, s3 = 0.f;
            #pragma unroll
            for (int i = 0; i < HD / 16; i++) {
                float4 a = kv[4 * i + 0], b4 = kv[4 * i + 1], c4 = kv[4 * i + 2], d4 = kv[4 * i + 3];
                s0 = fmaf(qr[16 * i + 0], a.x, s0);  s1 = fmaf(qr[16 * i + 1], a.y, s1);
                s2 = fmaf(qr[16 * i + 2], a.z, s2);  s3 = fmaf(qr[16 * i + 3], a.w, s3);
                s0 = fmaf(qr[16 * i + 4], b4.x, s0); s1 = fmaf(qr[16 * i + 5], b4.y, s1);
                s2 = fmaf(qr[16 * i + 6], b4.z, s2); s3 = fmaf(qr[16 * i + 7], b4.w, s3);
                s0 = fmaf(qr[16 * i + 8], c4.x, s0); s1 = fmaf(qr[16 * i + 9], c4.y, s1);
                s2 = fmaf(qr[16 * i + 10], c4.z, s2); s3 = fmaf(qr[16 * i + 11], c4.w, s3);
                s0 = fmaf(qr[16 * i + 12], d4.x, s0); s1 = fmaf(qr[16 * i + 13], d4.y, s1);
                s2 = fmaf(qr[16 * i + 14], d4.z, s2); s3 = fmaf(qr[16 * i + 15], d4.w, s3);
            }
            float s = (s0 + s1) + (s2 + s3);
            int mh = m >> 4, mw = m & 15;
            int idx = (th - mh + 15) * 31 + (tw - mw + 15);
            s += pos_s[idx] + mrow_s[mm];

            if (s > mx) {
                float corr = fast_exp(mx - s);
                ssum *= corr;
                #pragma unroll
                for (int d = 0; d < HD; d++) acc[d] *= corr;
                mx = s;
            }
            float p = fast_exp(s - mx);
            ssum += p;
            const float4* vv = (const float4*)(v_s + m * HD);
            #pragma unroll
            for (int i = 0; i < HD / 4; i++) {
                float4 v4 = vv[i];
                acc[4 * i + 0] = fmaf(p, v4.x, acc[4 * i + 0]);
                acc[4 * i + 1] = fmaf(p, v4.y, acc[4 * i + 1]);
                acc[4 * i + 2] = fmaf(p, v4.z, acc[4 * i + 2]);
                acc[4 * i + 3] = fmaf(p, v4.w, acc[4 * i + 3]);
            }
        }
    }

    float inv = 1.0f / ssum;
    float* orow = g_x + ((size_t)b * NTOK + t) * DIMC + h * HD;
    #pragma unroll
    for (int i = 0; i < HD / 4; i++) {
        float4 o;
        o.x = acc[4 * i + 0] * inv; o.y = acc[4 * i + 1] * inv;
        o.z = acc[4 * i + 2] * inv; o.w = acc[4 * i + 3] * inv;
        ((float4*)orow)[i] = o;
    }
}

// ---------------- launch ----------------------------------------------------
extern "C" void kernel_launch(void* const* d_in, const int* in_sizes, int n_in,
                              void* d_out, int out_size)
{
    const float* q      = (const float*)d_in[0];
    const float* k      = (const float*)d_in[1];
    const float* mask   = (const float*)d_in[2];
    const float* q_w    = (const float*)d_in[3];
    const float* q_b    = (const float*)d_in[4];
    const float* kv_w   = (const float*)d_in[5];
    const float* kv_b   = (const float*)d_in[6];
    const float* proj_w = (const float*)d_in[7];
    const float* proj_b = (const float*)d_in[8];
    const float* pp_w   = (const float*)d_in[9];
    const float* pp_b   = (const float*)d_in[10];
    const float* ln1_g  = (const float*)d_in[11];
    const float* ln1_b  = (const float*)d_in[12];
    const float* l1_w   = (const float*)d_in[13];
    const float* l1_b   = (const float*)d_in[14];
    const float* ln2_g  = (const float*)d_in[15];
    const float* ln2_b  = (const float*)d_in[16];
    const float* l2_w   = (const float*)d_in[17];
    const float* l2_b   = (const float*)d_in[18];
    const float* ln3_g  = (const float*)d_in[19];
    const float* ln3_b  = (const float*)d_in[20];
    const float* l3_w   = (const float*)d_in[21];
    const float* l3_b   = (const float*)d_in[22];
    float* out = (float*)d_out;

    static int attr_set = 0;
    if (!attr_set) {
        cudaFuncSetAttribute(attn_kernel, cudaFuncAttributeMaxDynamicSharedMemorySize,
                             (int)SMEM_ATTN);
        cudaFuncSetAttribute(gemm_mma<0>, cudaFuncAttributeMaxDynamicSharedMemorySize,
                             GEMM_SMEM);
        cudaFuncSetAttribute(gemm_mma<1>, cudaFuncAttributeMaxDynamicSharedMemorySize,
                             GEMM_SMEM);
        cudaFuncSetAttribute(gemm_mma<2>, cudaFuncAttributeMaxDynamicSharedMemorySize,
                             GEMM_SMEM);
        attr_set = 1;
    }

    pos_mlp_kernel<<<1, 992>>>(pp_w, pp_b, ln1_g, ln1_b, l1_w, l1_b,
                               ln2_g, ln2_b, l2_w, l2_b, ln3_g, ln3_b, l3_w, l3_b);

    // Q projection: (65536,256) @ (256,256)^T -> qh layout
    gemm_mma<0><<<dim3(512, 2), 256, GEMM_SMEM>>>(q, q_w, q_b, nullptr);
    // KV projection: (65536,256) @ (512,256)^T -> kh/vh layouts
    gemm_mma<1><<<dim3(512, 4), 256, GEMM_SMEM>>>(k, kv_w, kv_b, nullptr);
    // fused attention
    attn_kernel<<<BATCH * NHEADS, 256, SMEM_ATTN>>>(mask);
    // output projection: (65536,256) @ (256,256)^T -> d_out
    gemm_mma<2><<<dim3(512, 2), 256, GEMM_SMEM>>>(nullptr, proj_w, proj_b, out);
}

// round 15
// speedup vs baseline: 2.1231x; 1.2760x over previous
#include <cuda_runtime.h>
#include <cstdint>

#define BATCH 256
#define NTOK 256
#define DIMC 256
#define NHEADS 8
#define HD 32
#define NGROUP 64
#define LPOS 961   // (2*16-1)*(2*16-1)

// ---------------- scratch (static device globals; no runtime allocation) ----
__device__ float g_qh[(size_t)BATCH * NHEADS * NTOK * HD];
__device__ float g_kh[(size_t)BATCH * NHEADS * NTOK * HD];
__device__ float g_vh[(size_t)BATCH * NHEADS * NTOK * HD];
__device__ float g_x [(size_t)BATCH * NTOK * DIMC];
__device__ float g_pos[LPOS * NHEADS];

// ---------------- helpers ----------------------------------------------------
__device__ __forceinline__ uint32_t smem_u32(const void* p) {
    uint32_t a;
    asm("{ .reg .u64 t; cvta.to.shared.u64 t, %1; cvt.u32.u64 %0, t; }"
        : "=r"(a) : "l"(p));
    return a;
}
__device__ __forceinline__ uint32_t f2bf(float f) {   // fp32 -> bf16 bits (RNE)
    uint32_t u = __float_as_uint(f);
    return (u + 0x7fffu + ((u >> 16) & 1u)) >> 16;
}
__device__ __forceinline__ float rbf(float a) {       // residual after bf16 round
    return a - __uint_as_float(f2bf(a) << 16);
}
__device__ __forceinline__ void split2(float a, float b, uint32_t& hi, uint32_t& lo) {
    uint32_t ha = f2bf(a), hb = f2bf(b);
    float ra = a - __uint_as_float(ha << 16);
    float rb = b - __uint_as_float(hb << 16);
    hi = ha | (hb << 16);
    lo = f2bf(ra) | (f2bf(rb) << 16);
}
__device__ __forceinline__ void ldx4(uint32_t* r, uint32_t addr) {
    asm volatile("ldmatrix.sync.aligned.m8n8.x4.shared.b16 {%0,%1,%2,%3}, [%4];"
                 : "=r"(r[0]), "=r"(r[1]), "=r"(r[2]), "=r"(r[3]) : "r"(addr));
}
__device__ __forceinline__ void ldx2(uint32_t& r0, uint32_t& r1, uint32_t addr) {
    asm volatile("ldmatrix.sync.aligned.m8n8.x2.shared.b16 {%0,%1}, [%2];"
                 : "=r"(r0), "=r"(r1) : "r"(addr));
}
__device__ __forceinline__ void mma16816(float* c, const uint32_t* a,
                                         uint32_t b0, uint32_t b1) {
    asm volatile(
        "mma.sync.aligned.m16n8k16.row.col.f32.bf16.bf16.f32 "
        "{%0,%1,%2,%3}, {%4,%5,%6,%7}, {%8,%9}, {%0,%1,%2,%3};"
        : "+f"(c[0]), "+f"(c[1]), "+f"(c[2]), "+f"(c[3])
        : "r"(a[0]), "r"(a[1]), "r"(a[2]), "r"(a[3]), "r"(b0), "r"(b1));
}

// ---------------- fast exp: FFMA-only ---------------------------------------
__device__ __forceinline__ float fast_exp(float x) {
    x = fmaxf(x, -80.0f);
    float y = x * 1.4426950408889634f;
    float t = y + 12582912.0f;
    float n = t - 12582912.0f;
    float f = y - n;
    int   ni = (int)n;
    float r = 1.3333558146e-3f;
    r = fmaf(r, f, 9.6181291918e-3f);
    r = fmaf(r, f, 5.5504108665e-2f);
    r = fmaf(r, f, 2.4022650696e-1f);
    r = fmaf(r, f, 6.9314718056e-1f);
    r = fmaf(r, f, 1.0f);
    return r * __int_as_float((ni + 127) << 23);
}

// ---------------- DynamicPosBias MLP ----------------------------------------
__device__ __forceinline__ void lnorm16(float* x, const float* g, const float* b) {
    float m = 0.f;
    #pragma unroll
    for (int i = 0; i < 16; i++) m += x[i];
    m *= (1.0f / 16.0f);
    float v = 0.f;
    #pragma unroll
    for (int i = 0; i < 16; i++) { float d = x[i] - m; v += d * d; }
    v *= (1.0f / 16.0f);
    float r = rsqrtf(v + 1e-5f);
    #pragma unroll
    for (int i = 0; i < 16; i++) x[i] = (x[i] - m) * r * g[i] + b[i];
}

__global__ void pos_mlp_kernel(
    const float* __restrict__ pp_w, const float* __restrict__ pp_b,
    const float* __restrict__ ln1_g, const float* __restrict__ ln1_b,
    const float* __restrict__ l1_w, const float* __restrict__ l1_b,
    const float* __restrict__ ln2_g, const float* __restrict__ ln2_b,
    const float* __restrict__ l2_w, const float* __restrict__ l2_b,
    const float* __restrict__ ln3_g, const float* __restrict__ ln3_b,
    const float* __restrict__ l3_w, const float* __restrict__ l3_b)
{
    int l = blockIdx.x * blockDim.x + threadIdx.x;
    if (l >= LPOS) return;
    float b0 = (float)(l / 31) - 15.0f;
    float b1 = (float)(l % 31) - 15.0f;
    float x[16], y[16];
    #pragma unroll
    for (int p = 0; p < 16; p++)
        x[p] = fmaf(b0, pp_w[p * 2 + 0], fmaf(b1, pp_w[p * 2 + 1], pp_b[p]));
    lnorm16(x, ln1_g, ln1_b);
    #pragma unroll
    for (int p = 0; p < 16; p++) {
        float s = l1_b[p];
        #pragma unroll
        for (int q = 0; q < 16; q++) s = fmaf(fmaxf(x[q], 0.f), l1_w[p * 16 + q], s);
        y[p] = s;
    }
    lnorm16(y, ln2_g, ln2_b);
    #pragma unroll
    for (int p = 0; p < 16; p++) {
        float s = l2_b[p];
        #pragma unroll
        for (int q = 0; q < 16; q++) s = fmaf(fmaxf(y[q], 0.f), l2_w[p * 16 + q], s);
        x[p] = s;
    }
    lnorm16(x, ln3_g, ln3_b);
    #pragma unroll
    for (int h = 0; h < NHEADS; h++) {
        float s = l3_b[h];
        #pragma unroll
        for (int q = 0; q < 16; q++) s = fmaf(fmaxf(x[q], 0.f), l3_w[h * 16 + q], s);
        g_pos[l * NHEADS + h] = s;
    }
}

// ---------------- HMMA GEMM (unchanged from R14, measured-good) -------------
#define KSB 144
#define AH_OFF 1024
#define AL_OFF (AH_OFF + 128 * KSB)
#define WH_OFF (AL_OFF + 128 * KSB)
#define WL_OFF (WH_OFF + 128 * KSB)
#define GEMM_SMEM (WL_OFF + 128 * KSB)

template<int MODE>
__global__ __launch_bounds__(256)
void gemm_mma(const float* __restrict__ A_in,
              const float* __restrict__ Wt,
              const float* __restrict__ bias,
              float* __restrict__ Oout)
{
    extern __shared__ __align__(16) char smem[];
    const float* A = (MODE == 2) ? g_x : A_in;
    int tid = threadIdx.x;
    int rowBase = blockIdx.x * 128;
    int colBase = blockIdx.y * 128;
    uint32_t sb = smem_u32(smem);
    float* bias_s = (float*)smem;
    if (tid < 128) bias_s[tid] = bias[colBase + tid];

    int wid = tid >> 5, l = tid & 31;
    int wm = wid >> 2, wn = wid & 3;

    float c[4][4][4];
    #pragma unroll
    for (int i = 0; i < 4; i++)
        #pragma unroll
        for (int j = 0; j < 4; j++)
            #pragma unroll
            for (int k = 0; k < 4; k++) c[i][j][k] = 0.f;

    int mid = l >> 3;
    uint32_t aOffBase = (uint32_t)((wm * 64 + (mid & 1) * 8 + (l & 7)) * KSB
                                   + (mid >> 1) * 16);
    uint32_t bOffBase = (uint32_t)((wn * 32 + (l & 7)) * KSB + ((l >> 3) & 1) * 16);

    for (int ch = 0; ch < 4; ch++) {
        int k0 = ch * 64;
        __syncthreads();
        #pragma unroll
        for (int i = 0; i < 8; i++) {
            int idx = i * 256 + tid, row = idx >> 4, q4 = idx & 15;
            float4 v = *(const float4*)&A[(size_t)(rowBase + row) * 256 + k0 + q4 * 4];
            uint32_t h01, l01, h23, l23;
            split2(v.x, v.y, h01, l01);
            split2(v.z, v.w, h23, l23);
            uint32_t off = (uint32_t)(row * KSB + q4 * 8);
            *(uint2*)(smem + AH_OFF + off) = make_uint2(h01, h23);
            *(uint2*)(smem + AL_OFF + off) = make_uint2(l01, l23);
        }
        #pragma unroll
        for (int i = 0; i < 8; i++) {
            int idx = i * 256 + tid, row = idx >> 4, q4 = idx & 15;
            float4 v = *(const float4*)&Wt[(size_t)(colBase + row) * 256 + k0 + q4 * 4];
            uint32_t h01, l01, h23, l23;
            split2(v.x, v.y, h01, l01);
            split2(v.z, v.w, h23, l23);
            uint32_t off = (uint32_t)(row * KSB + q4 * 8);
            *(uint2*)(smem + WH_OFF + off) = make_uint2(h01, h23);
            *(uint2*)(smem + WL_OFF + off) = make_uint2(l01, l23);
        }
        __syncthreads();

        #pragma unroll
        for (int ks = 0; ks < 4; ks++) {
            uint32_t ah[4][4], al[4][4];
            #pragma unroll
            for (int mt = 0; mt < 4; mt++) {
                uint32_t ao = aOffBase + (uint32_t)(mt * 16 * KSB + ks * 32);
                ldx4(ah[mt], sb + AH_OFF + ao);
                ldx4(al[mt], sb + AL_OFF + ao);
            }
            #pragma unroll
            for (int nt = 0; nt < 4; nt++) {
                uint32_t bo = bOffBase + (uint32_t)(nt * 8 * KSB + ks * 32);
                uint32_t bh0, bh1, bl0, bl1;
                ldx2(bh0, bh1, sb + WH_OFF + bo);
                ldx2(bl0, bl1, sb + WL_OFF + bo);
                #pragma unroll
                for (int mt = 0; mt < 4; mt++) {
                    mma16816(c[mt][nt], ah[mt], bh0, bh1);
                    mma16816(c[mt][nt], ah[mt], bl0, bl1);
                    mma16816(c[mt][nt], al[mt], bh0, bh1);
                }
            }
        }
    }

    int gRow = l >> 2, gc2 = (l & 3) * 2;
    #pragma unroll
    for (int mt = 0; mt < 4; mt++) {
        #pragma unroll
        for (int nt = 0; nt < 4; nt++) {
            int lc = wn * 32 + nt * 8 + gc2;
            int cg = colBase + lc;
            float bx = bias_s[lc], by = bias_s[lc + 1];
            #pragma unroll
            for (int half = 0; half < 2; half++) {
                int r = rowBase + wm * 64 + mt * 16 + gRow + half * 8;
                float2 o = make_float2(c[mt][nt][half * 2 + 0] + bx,
                                       c[mt][nt][half * 2 + 1] + by);
                if (MODE == 2) {
                    *(float2*)&Oout[(size_t)r * 256 + cg] = o;
                } else {
                    int b = r >> 8, t = r & 255;
                    if (MODE == 0) {
                        int h = cg >> 5, d = cg & 31;
                        *(float2*)&g_qh[((((size_t)b * NHEADS + h) * NTOK + t) * HD) + d] = o;
                    } else {
                        int hv = cg >> 8, cc = cg & 255;
                        int h = cc >> 5, d = cc & 31;
                        float* dst = hv ? g_vh : g_kh;
                        *(float2*)&dst[((((size_t)b * NHEADS + h) * NTOK + t) * HD) + d] = o;
                    }
                }
            }
        }
    }
}

// ---------------- HMMA flash attention: per (b,h) CTA, 8 warps --------------
// smem: K hi/lo (key-major, 80B rows), Vt hi/lo (dim-major, 528B rows),
//       pos table, mask tile (256 x 33 f32)
#define KH_OFF  0                       // 256*80       = 20480
#define KL_OFF  20480                   //              = 20480 -> 40960
#define VTH_OFF 40960                   // 32*528       = 16896 -> 57856
#define VTL_OFF 57856                   //              -> 74752
#define POS_OFF 74752                   // 961*4 = 3844 -> 78596 pad 78608
#define AMT_OFF 78608                   // 256*33*4     = 33792 -> 112400
#define ATTN_SMEM 112400

__global__ __launch_bounds__(256)
void attn_kernel(const float* __restrict__ mask)
{
    extern __shared__ __align__(16) char smem[];
    int bh = blockIdx.x, b = bh >> 3, h = bh & 7;
    int tid = threadIdx.x, w = tid >> 5, l = tid & 31;
    int gid = l >> 2, qd = l & 3;

    // ---- stage K (hi/lo) and V transposed (hi/lo) -----
    const float* gk = g_kh + (size_t)bh * NTOK * HD;
    const float* gv = g_vh + (size_t)bh * NTOK * HD;
    for (int i = tid; i < NTOK * HD / 4; i += 256) {
        int row = i >> 3, q4 = i & 7;
        float4 kv = ((const float4*)gk)[i];
        uint32_t h01, l01, h23, l23;
        split2(kv.x, kv.y, h01, l01);
        split2(kv.z, kv.w, h23, l23);
        uint32_t off = (uint32_t)(row * 80 + q4 * 8);
        *(uint2*)(smem + KH_OFF + off) = make_uint2(h01, h23);
        *(uint2*)(smem + KL_OFF + off) = make_uint2(l01, l23);
        float4 vv = ((const float4*)gv)[i];
        float vals[4] = {vv.x, vv.y, vv.z, vv.w};
        #pragma unroll
        for (int j = 0; j < 4; j++) {
            int dim = q4 * 4 + j;
            uint32_t hi = f2bf(vals[j]);
            uint32_t lo = f2bf(vals[j] - __uint_as_float(hi << 16));
            *(uint16_t*)(smem + VTH_OFF + dim * 528 + row * 2) = (uint16_t)hi;
            *(uint16_t*)(smem + VTL_OFF + dim * 528 + row * 2) = (uint16_t)lo;
        }
    }
    float* pos_s = (float*)(smem + POS_OFF);
    for (int i = tid; i < LPOS; i += 256) pos_s[i] = g_pos[i * NHEADS + h];

    // ---- Q fragments in registers (scaled, hi/lo) ----
    const float* gq = g_qh + (size_t)bh * NTOK * HD;
    int qrow0 = w * 32;
    const float scale = 0.17677669529663687f;
    uint32_t qhi[2][2][4], qlo[2][2][4];
    #pragma unroll
    for (int mt = 0; mt < 2; mt++)
        #pragma unroll
        for (int ks = 0; ks < 2; ks++) {
            int r0 = qrow0 + mt * 16 + gid;
            #pragma unroll
            for (int rr = 0; rr < 4; rr++) {
                int r = r0 + (rr & 1) * 8;
                int d = ks * 16 + qd * 2 + (rr >> 1) * 8;
                float2 v = *(const float2*)&gq[r * 32 + d];
                split2(v.x * scale, v.y * scale, qhi[mt][ks][rr], qlo[mt][ks][rr]);
            }
        }

    float* mtile = (float*)(smem + AMT_OFF);
    const float* mbase = mask + (size_t)(b & (NGROUP - 1)) * NTOK * NTOK;

    int rowc[4];
    const float* mrow[4];
    #pragma unroll
    for (int r4 = 0; r4 < 4; r4++) {
        int t = qrow0 + (r4 >> 1) * 16 + gid + (r4 & 1) * 8;
        rowc[r4] = (t >> 4) * 31 + (t & 15) + 480;   // 15*31+15
        mrow[r4] = &mtile[t * 33];
    }

    float O[2][4][4];
    #pragma unroll
    for (int i = 0; i < 2; i++)
        #pragma unroll
        for (int j = 0; j < 4; j++)
            #pragma unroll
            for (int k = 0; k < 4; k++) O[i][j][k] = 0.f;
    float mx[4] = {-1e30f, -1e30f, -1e30f, -1e30f};
    float sm_[4] = {0.f, 0.f, 0.f, 0.f};

    for (int m0 = 0; m0 < NTOK; m0 += 32) {
        // ---- mask tile (coalesced gmem -> smem) ----
        __syncthreads();
        #pragma unroll
        for (int i = 0; i < 8; i++) {
            int f = i * 256 + tid;
            int r = f >> 3, q = f & 7;
            float4 v4 = *(const float4*)&mbase[(size_t)r * NTOK + m0 + 4 * q];
            float* dst = &mtile[r * 33 + 4 * q];
            dst[0] = v4.x; dst[1] = v4.y; dst[2] = v4.z; dst[3] = v4.w;
        }
        __syncthreads();

        // ---- S = Q K^T (3-term bf16) ----
        float s[2][4][4];
        #pragma unroll
        for (int i = 0; i < 2; i++)
            #pragma unroll
            for (int j = 0; j < 4; j++)
                #pragma unroll
                for (int k = 0; k < 4; k++) s[i][j][k] = 0.f;
        #pragma unroll
        for (int nt = 0; nt < 4; nt++) {
            int key = m0 + nt * 8 + gid;
            #pragma unroll
            for (int ks = 0; ks < 2; ks++) {
                uint32_t ko = (uint32_t)(key * 80 + ks * 32 + qd * 4);
                uint32_t bh0 = *(uint32_t*)(smem + KH_OFF + ko);
                uint32_t bh1 = *(uint32_t*)(smem + KH_OFF + ko + 16);
                uint32_t bl0 = *(uint32_t*)(smem + KL_OFF + ko);
                uint32_t bl1 = *(uint32_t*)(smem + KL_OFF + ko + 16);
                #pragma unroll
                for (int mt = 0; mt < 2; mt++) {
                    mma16816(s[mt][nt], qhi[mt][ks], bh0, bh1);
                    mma16816(s[mt][nt], qhi[mt][ks], bl0, bl1);
                    mma16816(s[mt][nt], qlo[mt][ks], bh0, bh1);
                }
            }
        }

        // ---- bias + mask + online softmax (per row quad) ----
        #pragma unroll
        for (int r4 = 0; r4 < 4; r4++) {
            int mt = r4 >> 1, hf = r4 & 1;
            float tmax = -1e30f;
            #pragma unroll
            for (int nt = 0; nt < 4; nt++)
                #pragma unroll
                for (int jj = 0; jj < 2; jj++) {
                    int ml = nt * 8 + qd * 2 + jj;
                    int m = m0 + ml;
                    float val = s[mt][nt][hf * 2 + jj]
                              + pos_s[rowc[r4] - ((m >> 4) * 31 + (m & 15))]
                              + mrow[r4][ml];
                    s[mt][nt][hf * 2 + jj] = val;
                    tmax = fmaxf(tmax, val);
                }
            tmax = fmaxf(tmax, __shfl_xor_sync(0xffffffffu, tmax, 1));
            tmax = fmaxf(tmax, __shfl_xor_sync(0xffffffffu, tmax, 2));
            float nmx = fmaxf(mx[r4], tmax);
            float corr = fast_exp(mx[r4] - nmx);
            mx[r4] = nmx;
            float rs = 0.f;
            #pragma unroll
            for (int nt = 0; nt < 4; nt++)
                #pragma unroll
                for (int jj = 0; jj < 2; jj++) {
                    float p = fast_exp(s[mt][nt][hf * 2 + jj] - nmx);
                    s[mt][nt][hf * 2 + jj] = p;
                    rs += p;
                }
            rs += __shfl_xor_sync(0xffffffffu, rs, 1);
            rs += __shfl_xor_sync(0xffffffffu, rs, 2);
            sm_[r4] = sm_[r4] * corr + rs;
            #pragma unroll
            for (int ntd = 0; ntd < 4; ntd++) {
                O[mt][ntd][hf * 2 + 0] *= corr;
                O[mt][ntd][hf * 2 + 1] *= corr;
            }
        }

        // ---- O += P V (3-term bf16), P repacked from S accumulators ----
        #pragma unroll
        for (int kk = 0; kk < 2; kk++) {
            uint32_t pahi[2][4], palo[2][4];
            #pragma unroll
            for (int mt = 0; mt < 2; mt++)
                #pragma unroll
                for (int rr = 0; rr < 4; rr++) {
                    int nt = 2 * kk + (rr >> 1);
                    float p0 = s[mt][nt][(rr & 1) * 2 + 0];
                    float p1 = s[mt][nt][(rr & 1) * 2 + 1];
                    pahi[mt][rr] = f2bf(p0) | (f2bf(p1) << 16);
                    palo[mt][rr] = f2bf(rbf(p0)) | (f2bf(rbf(p1)) << 16);
                }
            #pragma unroll
            for (int ntd = 0; ntd < 4; ntd++) {
                uint32_t vo = (uint32_t)((ntd * 8 + gid) * 528
                                         + (m0 + kk * 16 + qd * 2) * 2);
                uint32_t vh0 = *(uint32_t*)(smem + VTH_OFF + vo);
                uint32_t vh1 = *(uint32_t*)(smem + VTH_OFF + vo + 16);
                uint32_t vl0 = *(uint32_t*)(smem + VTL_OFF + vo);
                uint32_t vl1 = *(uint32_t*)(smem + VTL_OFF + vo + 16);
                #pragma unroll
                for (int mt = 0; mt < 2; mt++) {
                    mma16816(O[mt][ntd], pahi[mt], vh0, vh1);
                    mma16816(O[mt][ntd], pahi[mt], vl0, vl1);
                    mma16816(O[mt][ntd], palo[mt], vh0, vh1);
                }
            }
        }
    }

    // ---- normalize + store ----
    float inv[4];
    #pragma unroll
    for (int r4 = 0; r4 < 4; r4++) inv[r4] = 1.0f / sm_[r4];
    #pragma unroll
    for (int mt = 0; mt < 2; mt++)
        #pragma unroll
        for (int ntd = 0; ntd < 4; ntd++)
            #pragma unroll
            for (int hf = 0; hf < 2; hf++) {
                int r4 = mt * 2 + hf;
                int t = qrow0 + mt * 16 + gid + hf * 8;
                int d = ntd * 8 + qd * 2;
                float2 o = make_float2(O[mt][ntd][hf * 2 + 0] * inv[r4],
                                       O[mt][ntd][hf * 2 + 1] * inv[r4]);
                *(float2*)&g_x[((size_t)b * NTOK + t) * DIMC + h * HD + d] = o;
            }
}

// ---------------- launch ----------------------------------------------------
extern "C" void kernel_launch(void* const* d_in, const int* in_sizes, int n_in,
                              void* d_out, int out_size)
{
    const float* q      = (const float*)d_in[0];
    const float* k      = (const float*)d_in[1];
    const float* mask   = (const float*)d_in[2];
    const float* q_w    = (const float*)d_in[3];
    const float* q_b    = (const float*)d_in[4];
    const float* kv_w   = (const float*)d_in[5];
    const float* kv_b   = (const float*)d_in[6];
    const float* proj_w = (const float*)d_in[7];
    const float* proj_b = (const float*)d_in[8];
    const float* pp_w   = (const float*)d_in[9];
    const float* pp_b   = (const float*)d_in[10];
    const float* ln1_g  = (const float*)d_in[11];
    const float* ln1_b  = (const float*)d_in[12];
    const float* l1_w   = (const float*)d_in[13];
    const float* l1_b   = (const float*)d_in[14];
    const float* ln2_g  = (const float*)d_in[15];
    const float* ln2_b  = (const float*)d_in[16];
    const float* l2_w   = (const float*)d_in[17];
    const float* l2_b   = (const float*)d_in[18];
    const float* ln3_g  = (const float*)d_in[19];
    const float* ln3_b  = (const float*)d_in[20];
    const float* l3_w   = (const float*)d_in[21];
    const float* l3_b   = (const float*)d_in[22];
    float* out = (float*)d_out;

    static int attr_set = 0;
    if (!attr_set) {
        cudaFuncSetAttribute(attn_kernel, cudaFuncAttributeMaxDynamicSharedMemorySize,
                             ATTN_SMEM);
        cudaFuncSetAttribute(gemm_mma<0>, cudaFuncAttributeMaxDynamicSharedMemorySize,
                             GEMM_SMEM);
        cudaFuncSetAttribute(gemm_mma<1>, cudaFuncAttributeMaxDynamicSharedMemorySize,
                             GEMM_SMEM);
        cudaFuncSetAttribute(gemm_mma<2>, cudaFuncAttributeMaxDynamicSharedMemorySize,
                             GEMM_SMEM);
        attr_set = 1;
    }

    pos_mlp_kernel<<<1, 992>>>(pp_w, pp_b, ln1_g, ln1_b, l1_w, l1_b,
                               ln2_g, ln2_b, l2_w, l2_b, ln3_g, ln3_b, l3_w, l3_b);

    gemm_mma<0><<<dim3(512, 2), 256, GEMM_SMEM>>>(q, q_w, q_b, nullptr);
    gemm_mma<1><<<dim3(512, 4), 256, GEMM_SMEM>>>(k, kv_w, kv_b, nullptr);
    attn_kernel<<<BATCH * NHEADS, 256, ATTN_SMEM>>>(mask);
    gemm_mma<2><<<dim3(512, 2), 256, GEMM_SMEM>>>(nullptr, proj_w, proj_b, out);
}

// round 17
// speedup vs baseline: 2.5318x; 1.1925x over previous
#include <cuda_runtime.h>
#include <cstdint>

#define BATCH 256
#define NTOK 256
#define DIMC 256
#define NHEADS 8
#define HD 32
#define NGROUP 64
#define LPOS 961   // (2*16-1)*(2*16-1)

// ---------------- scratch (static device globals; no runtime allocation) ----
__device__ float g_qh[(size_t)BATCH * NHEADS * NTOK * HD];
__device__ float g_kh[(size_t)BATCH * NHEADS * NTOK * HD];
__device__ float g_vh[(size_t)BATCH * NHEADS * NTOK * HD];
__device__ float g_x [(size_t)BATCH * NTOK * DIMC];
__device__ float g_pos[LPOS * NHEADS];

// ---------------- helpers ----------------------------------------------------
__device__ __forceinline__ uint32_t smem_u32(const void* p) {
    uint32_t a;
    asm("{ .reg .u64 t; cvta.to.shared.u64 t, %1; cvt.u32.u64 %0, t; }"
        : "=r"(a) : "l"(p));
    return a;
}
__device__ __forceinline__ uint32_t f2bf(float f) {   // fp32 -> bf16 bits (RNE)
    uint32_t u = __float_as_uint(f);
    return (u + 0x7fffu + ((u >> 16) & 1u)) >> 16;
}
__device__ __forceinline__ float rbf(float a) {       // residual after bf16 round
    return a - __uint_as_float(f2bf(a) << 16);
}
__device__ __forceinline__ void split2(float a, float b, uint32_t& hi, uint32_t& lo) {
    uint32_t ha = f2bf(a), hb = f2bf(b);
    float ra = a - __uint_as_float(ha << 16);
    float rb = b - __uint_as_float(hb << 16);
    hi = ha | (hb << 16);
    lo = f2bf(ra) | (f2bf(rb) << 16);
}
__device__ __forceinline__ void ldx4(uint32_t* r, uint32_t addr) {
    asm volatile("ldmatrix.sync.aligned.m8n8.x4.shared.b16 {%0,%1,%2,%3}, [%4];"
                 : "=r"(r[0]), "=r"(r[1]), "=r"(r[2]), "=r"(r[3]) : "r"(addr));
}
__device__ __forceinline__ void ldx2(uint32_t& r0, uint32_t& r1, uint32_t addr) {
    asm volatile("ldmatrix.sync.aligned.m8n8.x2.shared.b16 {%0,%1}, [%2];"
                 : "=r"(r0), "=r"(r1) : "r"(addr));
}
__device__ __forceinline__ void mma16816(float* c, const uint32_t* a,
                                         uint32_t b0, uint32_t b1) {
    asm volatile(
        "mma.sync.aligned.m16n8k16.row.col.f32.bf16.bf16.f32 "
        "{%0,%1,%2,%3}, {%4,%5,%6,%7}, {%8,%9}, {%0,%1,%2,%3};"
        : "+f"(c[0]), "+f"(c[1]), "+f"(c[2]), "+f"(c[3])
        : "r"(a[0]), "r"(a[1]), "r"(a[2]), "r"(a[3]), "r"(b0), "r"(b1));
}

// ---------------- fast exp: FFMA-only ---------------------------------------
__device__ __forceinline__ float fast_exp(float x) {
    x = fmaxf(x, -80.0f);
    float y = x * 1.4426950408889634f;
    float t = y + 12582912.0f;
    float n = t - 12582912.0f;
    float f = y - n;
    int   ni = (int)n;
    float r = 1.3333558146e-3f;
    r = fmaf(r, f, 9.6181291918e-3f);
    r = fmaf(r, f, 5.5504108665e-2f);
    r = fmaf(r, f, 2.4022650696e-1f);
    r = fmaf(r, f, 6.9314718056e-1f);
    r = fmaf(r, f, 1.0f);
    return r * __int_as_float((ni + 127) << 23);
}

// ---------------- DynamicPosBias MLP ----------------------------------------
__device__ __forceinline__ void lnorm16(float* x, const float* g, const float* b) {
    float m = 0.f;
    #pragma unroll
    for (int i = 0; i < 16; i++) m += x[i];
    m *= (1.0f / 16.0f);
    float v = 0.f;
    #pragma unroll
    for (int i = 0; i < 16; i++) { float d = x[i] - m; v += d * d; }
    v *= (1.0f / 16.0f);
    float r = rsqrtf(v + 1e-5f);
    #pragma unroll
    for (int i = 0; i < 16; i++) x[i] = (x[i] - m) * r * g[i] + b[i];
}

__global__ void pos_mlp_kernel(
    const float* __restrict__ pp_w, const float* __restrict__ pp_b,
    const float* __restrict__ ln1_g, const float* __restrict__ ln1_b,
    const float* __restrict__ l1_w, const float* __restrict__ l1_b,
    const float* __restrict__ ln2_g, const float* __restrict__ ln2_b,
    const float* __restrict__ l2_w, const float* __restrict__ l2_b,
    const float* __restrict__ ln3_g, const float* __restrict__ ln3_b,
    const float* __restrict__ l3_w, const float* __restrict__ l3_b)
{
    int l = blockIdx.x * blockDim.x + threadIdx.x;
    if (l >= LPOS) return;
    float b0 = (float)(l / 31) - 15.0f;
    float b1 = (float)(l % 31) - 15.0f;
    float x[16], y[16];
    #pragma unroll
    for (int p = 0; p < 16; p++)
        x[p] = fmaf(b0, pp_w[p * 2 + 0], fmaf(b1, pp_w[p * 2 + 1], pp_b[p]));
    lnorm16(x, ln1_g, ln1_b);
    #pragma unroll
    for (int p = 0; p < 16; p++) {
        float s = l1_b[p];
        #pragma unroll
        for (int q = 0; q < 16; q++) s = fmaf(fmaxf(x[q], 0.f), l1_w[p * 16 + q], s);
        y[p] = s;
    }
    lnorm16(y, ln2_g, ln2_b);
    #pragma unroll
    for (int p = 0; p < 16; p++) {
        float s = l2_b[p];
        #pragma unroll
        for (int q = 0; q < 16; q++) s = fmaf(fmaxf(y[q], 0.f), l2_w[p * 16 + q], s);
        x[p] = s;
    }
    lnorm16(x, ln3_g, ln3_b);
    #pragma unroll
    for (int h = 0; h < NHEADS; h++) {
        float s = l3_b[h];
        #pragma unroll
        for (int q = 0; q < 16; q++) s = fmaf(fmaxf(x[q], 0.f), l3_w[h * 16 + q], s);
        g_pos[l * NHEADS + h] = s;
    }
}

// ---------------- HMMA GEMM (unchanged, measured-good) ----------------------
#define KSB 144
#define AH_OFF 1024
#define AL_OFF (AH_OFF + 128 * KSB)
#define WH_OFF (AL_OFF + 128 * KSB)
#define WL_OFF (WH_OFF + 128 * KSB)
#define GEMM_SMEM (WL_OFF + 128 * KSB)

template<int MODE>
__global__ __launch_bounds__(256)
void gemm_mma(const float* __restrict__ A_in,
              const float* __restrict__ Wt,
              const float* __restrict__ bias,
              float* __restrict__ Oout)
{
    extern __shared__ __align__(16) char smem[];
    const float* A = (MODE == 2) ? g_x : A_in;
    int tid = threadIdx.x;
    int rowBase = blockIdx.x * 128;
    int colBase = blockIdx.y * 128;
    uint32_t sb = smem_u32(smem);
    float* bias_s = (float*)smem;
    if (tid < 128) bias_s[tid] = bias[colBase + tid];

    int wid = tid >> 5, l = tid & 31;
    int wm = wid >> 2, wn = wid & 3;

    float c[4][4][4];
    #pragma unroll
    for (int i = 0; i < 4; i++)
        #pragma unroll
        for (int j = 0; j < 4; j++)
            #pragma unroll
            for (int k = 0; k < 4; k++) c[i][j][k] = 0.f;

    int mid = l >> 3;
    uint32_t aOffBase = (uint32_t)((wm * 64 + (mid & 1) * 8 + (l & 7)) * KSB
                                   + (mid >> 1) * 16);
    uint32_t bOffBase = (uint32_t)((wn * 32 + (l & 7)) * KSB + ((l >> 3) & 1) * 16);

    for (int ch = 0; ch < 4; ch++) {
        int k0 = ch * 64;
        __syncthreads();
        #pragma unroll
        for (int i = 0; i < 8; i++) {
            int idx = i * 256 + tid, row = idx >> 4, q4 = idx & 15;
            float4 v = *(const float4*)&A[(size_t)(rowBase + row) * 256 + k0 + q4 * 4];
            uint32_t h01, l01, h23, l23;
            split2(v.x, v.y, h01, l01);
            split2(v.z, v.w, h23, l23);
            uint32_t off = (uint32_t)(row * KSB + q4 * 8);
            *(uint2*)(smem + AH_OFF + off) = make_uint2(h01, h23);
            *(uint2*)(smem + AL_OFF + off) = make_uint2(l01, l23);
        }
        #pragma unroll
        for (int i = 0; i < 8; i++) {
            int idx = i * 256 + tid, row = idx >> 4, q4 = idx & 15;
            float4 v = *(const float4*)&Wt[(size_t)(colBase + row) * 256 + k0 + q4 * 4];
            uint32_t h01, l01, h23, l23;
            split2(v.x, v.y, h01, l01);
            split2(v.z, v.w, h23, l23);
            uint32_t off = (uint32_t)(row * KSB + q4 * 8);
            *(uint2*)(smem + WH_OFF + off) = make_uint2(h01, h23);
            *(uint2*)(smem + WL_OFF + off) = make_uint2(l01, l23);
        }
        __syncthreads();

        #pragma unroll
        for (int ks = 0; ks < 4; ks++) {
            uint32_t ah[4][4], al[4][4];
            #pragma unroll
            for (int mt = 0; mt < 4; mt++) {
                uint32_t ao = aOffBase + (uint32_t)(mt * 16 * KSB + ks * 32);
                ldx4(ah[mt], sb + AH_OFF + ao);
                ldx4(al[mt], sb + AL_OFF + ao);
            }
            #pragma unroll
            for (int nt = 0; nt < 4; nt++) {
                uint32_t bo = bOffBase + (uint32_t)(nt * 8 * KSB + ks * 32);
                uint32_t bh0, bh1, bl0, bl1;
                ldx2(bh0, bh1, sb + WH_OFF + bo);
                ldx2(bl0, bl1, sb + WL_OFF + bo);
                #pragma unroll
                for (int mt = 0; mt < 4; mt++) {
                    mma16816(c[mt][nt], ah[mt], bh0, bh1);
                    mma16816(c[mt][nt], ah[mt], bl0, bl1);
                    mma16816(c[mt][nt], al[mt], bh0, bh1);
                }
            }
        }
    }

    int gRow = l >> 2, gc2 = (l & 3) * 2;
    #pragma unroll
    for (int mt = 0; mt < 4; mt++) {
        #pragma unroll
        for (int nt = 0; nt < 4; nt++) {
            int lc = wn * 32 + nt * 8 + gc2;
            int cg = colBase + lc;
            float bx = bias_s[lc], by = bias_s[lc + 1];
            #pragma unroll
            for (int half = 0; half < 2; half++) {
                int r = rowBase + wm * 64 + mt * 16 + gRow + half * 8;
                float2 o = make_float2(c[mt][nt][half * 2 + 0] + bx,
                                       c[mt][nt][half * 2 + 1] + by);
                if (MODE == 2) {
                    *(float2*)&Oout[(size_t)r * 256 + cg] = o;
                } else {
                    int b = r >> 8, t = r & 255;
                    if (MODE == 0) {
                        int h = cg >> 5, d = cg & 31;
                        *(float2*)&g_qh[((((size_t)b * NHEADS + h) * NTOK + t) * HD) + d] = o;
                    } else {
                        int hv = cg >> 8, cc = cg & 255;
                        int h = cc >> 5, d = cc & 31;
                        float* dst = hv ? g_vh : g_kh;
                        *(float2*)&dst[((((size_t)b * NHEADS + h) * NTOK + t) * HD) + d] = o;
                    }
                }
            }
        }
    }
}

// ---------------- HMMA flash attention, no-max softmax ----------------------
// smem: K hi/lo (80B rows), Vt hi/lo (528B rows), pos, fused mask+pos tile
#define KH_OFF  0
#define KL_OFF  20480
#define VTH_OFF 40960
#define VTL_OFF 57856
#define POS_OFF 74752
#define AMT_OFF 78608                   // 256*33*4 = 33792 -> 112400
#define ATTN_SMEM 112400

__global__ __launch_bounds__(256)
void attn_kernel(const float* __restrict__ mask)
{
    extern __shared__ __align__(16) char smem[];
    int bh = blockIdx.x, b = bh >> 3, h = bh & 7;
    int tid = threadIdx.x, w = tid >> 5, l = tid & 31;
    int gid = l >> 2, qd = l & 3;

    // ---- stage K (hi/lo) and V transposed (hi/lo) -----
    const float* gk = g_kh + (size_t)bh * NTOK * HD;
    const float* gv = g_vh + (size_t)bh * NTOK * HD;
    for (int i = tid; i < NTOK * HD / 4; i += 256) {
        int row = i >> 3, q4 = i & 7;
        float4 kv = ((const float4*)gk)[i];
        uint32_t h01, l01, h23, l23;
        split2(kv.x, kv.y, h01, l01);
        split2(kv.z, kv.w, h23, l23);
        uint32_t off = (uint32_t)(row * 80 + q4 * 8);
        *(uint2*)(smem + KH_OFF + off) = make_uint2(h01, h23);
        *(uint2*)(smem + KL_OFF + off) = make_uint2(l01, l23);
        float4 vv = ((const float4*)gv)[i];
        float vals[4] = {vv.x, vv.y, vv.z, vv.w};
        #pragma unroll
        for (int j = 0; j < 4; j++) {
            int dim = q4 * 4 + j;
            uint32_t hi = f2bf(vals[j]);
            uint32_t lo = f2bf(vals[j] - __uint_as_float(hi << 16));
            *(uint16_t*)(smem + VTH_OFF + dim * 528 + row * 2) = (uint16_t)hi;
            *(uint16_t*)(smem + VTL_OFF + dim * 528 + row * 2) = (uint16_t)lo;
        }
    }
    float* pos_s = (float*)(smem + POS_OFF);
    for (int i = tid; i < LPOS; i += 256) pos_s[i] = g_pos[i * NHEADS + h];

    // ---- Q fragments in registers (scaled, hi/lo) ----
    const float* gq = g_qh + (size_t)bh * NTOK * HD;
    int qrow0 = w * 32;
    const float scale = 0.17677669529663687f;
    uint32_t qhi[2][2][4], qlo[2][2][4];
    #pragma unroll
    for (int mt = 0; mt < 2; mt++)
        #pragma unroll
        for (int ks = 0; ks < 2; ks++) {
            int r0 = qrow0 + mt * 16 + gid;
            #pragma unroll
            for (int rr = 0; rr < 4; rr++) {
                int r = r0 + (rr & 1) * 8;
                int d = ks * 16 + qd * 2 + (rr >> 1) * 8;
                float2 v = *(const float2*)&gq[r * 32 + d];
                split2(v.x * scale, v.y * scale, qhi[mt][ks][rr], qlo[mt][ks][rr]);
            }
        }

    float* mtile = (float*)(smem + AMT_OFF);
    const float* mbase = mask + (size_t)(b & (NGROUP - 1)) * NTOK * NTOK;

    const float* mrow[4];
    #pragma unroll
    for (int r4 = 0; r4 < 4; r4++) {
        int t = qrow0 + (r4 >> 1) * 16 + gid + (r4 & 1) * 8;
        mrow[r4] = &mtile[t * 33];
    }

    float O[2][4][4];
    #pragma unroll
    for (int i = 0; i < 2; i++)
        #pragma unroll
        for (int j = 0; j < 4; j++)
            #pragma unroll
            for (int k = 0; k < 4; k++) O[i][j][k] = 0.f;
    float sm_[4] = {0.f, 0.f, 0.f, 0.f};

    for (int m0 = 0; m0 < NTOK; m0 += 32) {
        // ---- mask tile staging, pos-bias fused in ----
        __syncthreads();
        #pragma unroll
        for (int i = 0; i < 8; i++) {
            int f = i * 256 + tid;
            int r = f >> 3, q = f & 7;
            int m = m0 + 4 * q;                       // 4 keys, same 16-block
            float4 v4 = *(const float4*)&mbase[(size_t)r * NTOK + m];
            int pidx = ((r >> 4) - (m >> 4) + 15) * 31 + (r & 15) - (m & 15) + 15;
            float* dst = &mtile[r * 33 + 4 * q];
            dst[0] = v4.x + pos_s[pidx];
            dst[1] = v4.y + pos_s[pidx - 1];
            dst[2] = v4.z + pos_s[pidx - 2];
            dst[3] = v4.w + pos_s[pidx - 3];
        }
        __syncthreads();

        // ---- S = Q K^T (3-term bf16) ----
        float s[2][4][4];
        #pragma unroll
        for (int i = 0; i < 2; i++)
            #pragma unroll
            for (int j = 0; j < 4; j++)
                #pragma unroll
                for (int k = 0; k < 4; k++) s[i][j][k] = 0.f;
        #pragma unroll
        for (int nt = 0; nt < 4; nt++) {
            int key = m0 + nt * 8 + gid;
            #pragma unroll
            for (int ks = 0; ks < 2; ks++) {
                uint32_t ko = (uint32_t)(key * 80 + ks * 32 + qd * 4);
                uint32_t bh0 = *(uint32_t*)(smem + KH_OFF + ko);
                uint32_t bh1 = *(uint32_t*)(smem + KH_OFF + ko + 16);
                uint32_t bl0 = *(uint32_t*)(smem + KL_OFF + ko);
                uint32_t bl1 = *(uint32_t*)(smem + KL_OFF + ko + 16);
                #pragma unroll
                for (int mt = 0; mt < 2; mt++) {
                    mma16816(s[mt][nt], qhi[mt][ks], bh0, bh1);
                    mma16816(s[mt][nt], qhi[mt][ks], bl0, bl1);
                    mma16816(s[mt][nt], qlo[mt][ks], bh0, bh1);
                }
            }
        }

        // ---- no-max softmax: p = exp(s + mask+pos), deferred sum ----
        #pragma unroll
        for (int r4 = 0; r4 < 4; r4++) {
            int mt = r4 >> 1, hf = r4 & 1;
            float rs = 0.f;
            #pragma unroll
            for (int nt = 0; nt < 4; nt++)
                #pragma unroll
                for (int jj = 0; jj < 2; jj++) {
                    int ml = nt * 8 + qd * 2 + jj;
                    float p = fast_exp(s[mt][nt][hf * 2 + jj] + mrow[r4][ml]);
                    s[mt][nt][hf * 2 + jj] = p;
                    rs += p;
                }
            sm_[r4] += rs;
        }

        // ---- O += P V (3-term bf16), P repacked from S accumulators ----
        #pragma unroll
        for (int kk = 0; kk < 2; kk++) {
            uint32_t pahi[2][4], palo[2][4];
            #pragma unroll
            for (int mt = 0; mt < 2; mt++)
                #pragma unroll
                for (int rr = 0; rr < 4; rr++) {
                    int nt = 2 * kk + (rr >> 1);
                    float p0 = s[mt][nt][(rr & 1) * 2 + 0];
                    float p1 = s[mt][nt][(rr & 1) * 2 + 1];
                    pahi[mt][rr] = f2bf(p0) | (f2bf(p1) << 16);
                    palo[mt][rr] = f2bf(rbf(p0)) | (f2bf(rbf(p1)) << 16);
                }
            #pragma unroll
            for (int ntd = 0; ntd < 4; ntd++) {
                uint32_t vo = (uint32_t)((ntd * 8 + gid) * 528
                                         + (m0 + kk * 16 + qd * 2) * 2);
                uint32_t vh0 = *(uint32_t*)(smem + VTH_OFF + vo);
                uint32_t vh1 = *(uint32_t*)(smem + VTH_OFF + vo + 16);
                uint32_t vl0 = *(uint32_t*)(smem + VTL_OFF + vo);
                uint32_t vl1 = *(uint32_t*)(smem + VTL_OFF + vo + 16);
                #pragma unroll
                for (int mt = 0; mt < 2; mt++) {
                    mma16816(O[mt][ntd], pahi[mt], vh0, vh1);
                    mma16816(O[mt][ntd], pahi[mt], vl0, vl1);
                    mma16816(O[mt][ntd], palo[mt], vh0, vh1);
                }
            }
        }
    }

    // ---- final sum reduction + normalize + store ----
    float inv[4];
    #pragma unroll
    for (int r4 = 0; r4 < 4; r4++) {
        float rs = sm_[r4];
        rs += __shfl_xor_sync(0xffffffffu, rs, 1);
        rs += __shfl_xor_sync(0xffffffffu, rs, 2);
        inv[r4] = 1.0f / rs;
    }
    #pragma unroll
    for (int mt = 0; mt < 2; mt++)
        #pragma unroll
        for (int ntd = 0; ntd < 4; ntd++)
            #pragma unroll
            for (int hf = 0; hf < 2; hf++) {
                int r4 = mt * 2 + hf;
                int t = qrow0 + mt * 16 + gid + hf * 8;
                int d = ntd * 8 + qd * 2;
                float2 o = make_float2(O[mt][ntd][hf * 2 + 0] * inv[r4],
                                       O[mt][ntd][hf * 2 + 1] * inv[r4]);
                *(float2*)&g_x[((size_t)b * NTOK + t) * DIMC + h * HD + d] = o;
            }
}

// ---------------- launch ----------------------------------------------------
extern "C" void kernel_launch(void* const* d_in, const int* in_sizes, int n_in,
                              void* d_out, int out_size)
{
    const float* q      = (const float*)d_in[0];
    const float* k      = (const float*)d_in[1];
    const float* mask   = (const float*)d_in[2];
    const float* q_w    = (const float*)d_in[3];
    const float* q_b    = (const float*)d_in[4];
    const float* kv_w   = (const float*)d_in[5];
    const float* kv_b   = (const float*)d_in[6];
    const float* proj_w = (const float*)d_in[7];
    const float* proj_b = (const float*)d_in[8];
    const float* pp_w   = (const float*)d_in[9];
    const float* pp_b   = (const float*)d_in[10];
    const float* ln1_g  = (const float*)d_in[11];
    const float* ln1_b  = (const float*)d_in[12];
    const float* l1_w   = (const float*)d_in[13];
    const float* l1_b   = (const float*)d_in[14];
    const float* ln2_g  = (const float*)d_in[15];
    const float* ln2_b  = (const float*)d_in[16];
    const float* l2_w   = (const float*)d_in[17];
    const float* l2_b   = (const float*)d_in[18];
    const float* ln3_g  = (const float*)d_in[19];
    const float* ln3_b  = (const float*)d_in[20];
    const float* l3_w   = (const float*)d_in[21];
    const float* l3_b   = (const float*)d_in[22];
    float* out = (float*)d_out;

    static int attr_set = 0;
    if (!attr_set) {
        cudaFuncSetAttribute(attn_kernel, cudaFuncAttributeMaxDynamicSharedMemorySize,
                             ATTN_SMEM);
        cudaFuncSetAttribute(gemm_mma<0>, cudaFuncAttributeMaxDynamicSharedMemorySize,
                             GEMM_SMEM);
        cudaFuncSetAttribute(gemm_mma<1>, cudaFuncAttributeMaxDynamicSharedMemorySize,
                             GEMM_SMEM);
        cudaFuncSetAttribute(gemm_mma<2>, cudaFuncAttributeMaxDynamicSharedMemorySize,
                             GEMM_SMEM);
        attr_set = 1;
    }

    pos_mlp_kernel<<<1, 992>>>(pp_w, pp_b, ln1_g, ln1_b, l1_w, l1_b,
                               ln2_g, ln2_b, l2_w, l2_b, ln3_g, ln3_b, l3_w, l3_b);

    gemm_mma<0><<<dim3(512, 2), 256, GEMM_SMEM>>>(q, q_w, q_b, nullptr);
    gemm_mma<1><<<dim3(512, 4), 256, GEMM_SMEM>>>(k, kv_w, kv_b, nullptr);
    attn_kernel<<<BATCH * NHEADS, 256, ATTN_SMEM>>>(mask);
    gemm_mma<2><<<dim3(512, 2), 256, GEMM_SMEM>>>(nullptr, proj_w, proj_b, out);
}